// round 2
// baseline (speedup 1.0000x reference)
#include <cuda_runtime.h>
#include <math.h>

#define BM 128
#define BN 128
#define BK 16

#define B_DIM   4096
#define IN_DIM  1024
#define OUT_DIM 1024

// Scratch (allocation-free rule: __device__ globals)
__device__ float g_act[(size_t)B_DIM * 2 * OUT_DIM];  // activated [4096, 2048]
__device__ float g_z  [(size_t)B_DIM * OUT_DIM];      // z         [4096, 1024]
__device__ float g_hr [(size_t)B_DIM * OUT_DIM];      // h_prev*r  [4096, 1024]

// ---------------------------------------------------------------------------
// Shared-memory tiled SGEMM mainloop.
// C-tile [BM x BN] at (m0, n0); A is a virtual row-wise concat of A0 (K0 cols,
// stride lda0) and A1 (stride lda1). B is row-major [Ktot, ldb].
// Thread layout: 256 threads = 16x16 (tx fast). Each thread owns an 8x8
// microtile at rows {ty*4..+3, 64+ty*4..+3} x cols {tx*4..+3, 64+tx*4..+3}.
// ---------------------------------------------------------------------------
__device__ __forceinline__ void gemm_main(
    const float* __restrict__ A0, int lda0, int K0,
    const float* __restrict__ A1, int lda1,
    const float* __restrict__ Bp, int ldb,
    int m0, int n0, int Ktot,
    float (&acc)[8][8])
{
    __shared__ float As[BK][BM + 4];   // row stride 132 floats = 528B (16B aligned)
    __shared__ float Bs[BK][BN];

    const int tid = threadIdx.x;
    const int tx = tid & 15;
    const int ty = tid >> 4;

#pragma unroll
    for (int i = 0; i < 8; i++)
#pragma unroll
        for (int j = 0; j < 8; j++) acc[i][j] = 0.0f;

    for (int k0 = 0; k0 < Ktot; k0 += BK) {
        // Pick A source for this K-tile (BK divides K0 for all our shapes)
        const float* Asrc;
        int lda, kk;
        if (k0 < K0) { Asrc = A0; lda = lda0; kk = k0; }
        else         { Asrc = A1; lda = lda1; kk = k0 - K0; }

        // --- load A tile [BM x BK] transposed into As[k][m] -----------------
#pragma unroll
        for (int l = 0; l < 2; l++) {
            int v  = tid + l * 256;        // 0..511
            int m  = v >> 2;               // 0..127
            int kq = (v & 3) * 4;          // 0,4,8,12
            float4 a = *(const float4*)(Asrc + (size_t)(m0 + m) * lda + kk + kq);
            As[kq + 0][m] = a.x;
            As[kq + 1][m] = a.y;
            As[kq + 2][m] = a.z;
            As[kq + 3][m] = a.w;
        }
        // --- load B tile [BK x BN] ------------------------------------------
#pragma unroll
        for (int l = 0; l < 2; l++) {
            int v  = tid + l * 256;
            int kr = v >> 5;               // 0..15
            int nq = (v & 31) * 4;         // 0..124
            *(float4*)&Bs[kr][nq] =
                *(const float4*)(Bp + (size_t)(k0 + kr) * ldb + n0 + nq);
        }
        __syncthreads();

#pragma unroll
        for (int k = 0; k < BK; k++) {
            float4 a0 = *(const float4*)&As[k][ty * 4];
            float4 a1 = *(const float4*)&As[k][64 + ty * 4];
            float4 b0 = *(const float4*)&Bs[k][tx * 4];
            float4 b1 = *(const float4*)&Bs[k][64 + tx * 4];
            float ra[8] = {a0.x, a0.y, a0.z, a0.w, a1.x, a1.y, a1.z, a1.w};
            float rb[8] = {b0.x, b0.y, b0.z, b0.w, b1.x, b1.y, b1.z, b1.w};
#pragma unroll
            for (int i = 0; i < 8; i++)
#pragma unroll
                for (int j = 0; j < 8; j++)
                    acc[i][j] = fmaf(ra[i], rb[j], acc[i][j]);
        }
        __syncthreads();
    }
}

__device__ __forceinline__ float sigmoidf_(float x) {
    return 1.0f / (1.0f + expf(-x));
}

// ---------------------------------------------------------------------------
// Kernel 1: new_x = [x | h_prev] @ W_in + b_in, fused spike epilogue.
//   pot_tmp  = pot_prev + new_x
//   spiked   = pot_tmp > tresh
//   activated= spiked ? pot_tmp : 0            -> g_act
//   pot_next = spiked ? 0 : pot_tmp * decay    -> out_pot
// ---------------------------------------------------------------------------
__global__ void __launch_bounds__(256, 2)
k_gemm_in(const float* __restrict__ x, const float* __restrict__ h_prev,
          const float* __restrict__ W_in, const float* __restrict__ b_in,
          const float* __restrict__ pot_prev,
          const float* __restrict__ tresh, const float* __restrict__ decay,
          float* __restrict__ out_pot)
{
    const int n0 = blockIdx.x * BN;
    const int m0 = blockIdx.y * BM;
    float acc[8][8];
    gemm_main(x, IN_DIM, IN_DIM, h_prev, OUT_DIM,
              W_in, 2 * OUT_DIM, m0, n0, IN_DIM + OUT_DIM, acc);

    const int tx = threadIdx.x & 15;
    const int ty = threadIdx.x >> 4;
    const int rows[2] = {ty * 4, 64 + ty * 4};
    const int cols[2] = {tx * 4, 64 + tx * 4};

#pragma unroll
    for (int ih = 0; ih < 2; ih++)
#pragma unroll
        for (int i = 0; i < 4; i++) {
            const int m = m0 + rows[ih] + i;
#pragma unroll
            for (int jh = 0; jh < 2; jh++)
#pragma unroll
                for (int j = 0; j < 4; j++) {
                    const int n = n0 + cols[jh] + j;
                    float c  = acc[ih * 4 + i][jh * 4 + j] + b_in[n];
                    float pt = pot_prev[(size_t)m * (2 * OUT_DIM) + n] + c;
                    bool  sp = pt > tresh[n];
                    g_act[(size_t)m * (2 * OUT_DIM) + n]   = sp ? pt : 0.0f;
                    out_pot[(size_t)m * (2 * OUT_DIM) + n] = sp ? 0.0f : pt * decay[n];
                }
        }
}

// ---------------------------------------------------------------------------
// Kernel 2: gru_combined = [activated | h_prev], K = 3072.
//   blocks with bx < 8:  z = sigmoid(.@W_z + b_z)       -> g_z
//   blocks with bx >= 8: r = sigmoid(.@W_r + b_r); h*r  -> g_hr
// ---------------------------------------------------------------------------
__global__ void __launch_bounds__(256, 2)
k_gemm_zr(const float* __restrict__ h_prev,
          const float* __restrict__ W_z, const float* __restrict__ b_z,
          const float* __restrict__ W_r, const float* __restrict__ b_r)
{
    const int bx = blockIdx.x;
    const bool is_z = (bx < 8);
    const float* Bp   = is_z ? W_z : W_r;
    const float* bias = is_z ? b_z : b_r;
    const int n0 = (is_z ? bx : bx - 8) * BN;
    const int m0 = blockIdx.y * BM;

    float acc[8][8];
    gemm_main(g_act, 2 * OUT_DIM, 2 * OUT_DIM, h_prev, OUT_DIM,
              Bp, OUT_DIM, m0, n0, 3 * OUT_DIM, acc);

    const int tx = threadIdx.x & 15;
    const int ty = threadIdx.x >> 4;
    const int rows[2] = {ty * 4, 64 + ty * 4};
    const int cols[2] = {tx * 4, 64 + tx * 4};

#pragma unroll
    for (int ih = 0; ih < 2; ih++)
#pragma unroll
        for (int i = 0; i < 4; i++) {
            const int m = m0 + rows[ih] + i;
#pragma unroll
            for (int jh = 0; jh < 2; jh++)
#pragma unroll
                for (int j = 0; j < 4; j++) {
                    const int n = n0 + cols[jh] + j;
                    float v = sigmoidf_(acc[ih * 4 + i][jh * 4 + j] + bias[n]);
                    if (is_z)
                        g_z[(size_t)m * OUT_DIM + n] = v;
                    else
                        g_hr[(size_t)m * OUT_DIM + n] =
                            h_prev[(size_t)m * OUT_DIM + n] * v;
                }
        }
}

// ---------------------------------------------------------------------------
// Kernel 3: cand_in = [activated | h*r], n = tanh(.@W_n + b_n)
//   h_next = (1-z)*h_prev + z*n  -> out_h
// ---------------------------------------------------------------------------
__global__ void __launch_bounds__(256, 2)
k_gemm_n(const float* __restrict__ h_prev,
         const float* __restrict__ W_n, const float* __restrict__ b_n,
         float* __restrict__ out_h)
{
    const int n0 = blockIdx.x * BN;
    const int m0 = blockIdx.y * BM;

    float acc[8][8];
    gemm_main(g_act, 2 * OUT_DIM, 2 * OUT_DIM, g_hr, OUT_DIM,
              W_n, OUT_DIM, m0, n0, 3 * OUT_DIM, acc);

    const int tx = threadIdx.x & 15;
    const int ty = threadIdx.x >> 4;
    const int rows[2] = {ty * 4, 64 + ty * 4};
    const int cols[2] = {tx * 4, 64 + tx * 4};

#pragma unroll
    for (int ih = 0; ih < 2; ih++)
#pragma unroll
        for (int i = 0; i < 4; i++) {
            const int m = m0 + rows[ih] + i;
#pragma unroll
            for (int jh = 0; jh < 2; jh++)
#pragma unroll
                for (int j = 0; j < 4; j++) {
                    const int n = n0 + cols[jh] + j;
                    float nv = tanhf(acc[ih * 4 + i][jh * 4 + j] + b_n[n]);
                    float z  = g_z[(size_t)m * OUT_DIM + n];
                    float h  = h_prev[(size_t)m * OUT_DIM + n];
                    out_h[(size_t)m * OUT_DIM + n] = (1.0f - z) * h + z * nv;
                }
        }
}

// ---------------------------------------------------------------------------
// Inputs (metadata order):
//  0 x[4096,1024] 1 h_prev[4096,1024] 2 pot_prev[4096,2048]
//  3 W_in[2048,2048] 4 b_in[2048] 5 tresh[2048] 6 decay[2048]
//  7 W_z[3072,1024] 8 b_z[1024] 9 W_r[3072,1024] 10 b_r[1024]
// 11 W_n[3072,1024] 12 b_n[1024]
// Output: h_next [4096,1024] then pot_next [4096,2048] (float32)
// ---------------------------------------------------------------------------
extern "C" void kernel_launch(void* const* d_in, const int* in_sizes, int n_in,
                              void* d_out, int out_size)
{
    const float* x        = (const float*)d_in[0];
    const float* h_prev   = (const float*)d_in[1];
    const float* pot_prev = (const float*)d_in[2];
    const float* W_in     = (const float*)d_in[3];
    const float* b_in     = (const float*)d_in[4];
    const float* tresh    = (const float*)d_in[5];
    const float* decay    = (const float*)d_in[6];
    const float* W_z      = (const float*)d_in[7];
    const float* b_z      = (const float*)d_in[8];
    const float* W_r      = (const float*)d_in[9];
    const float* b_r      = (const float*)d_in[10];
    const float* W_n      = (const float*)d_in[11];
    const float* b_n      = (const float*)d_in[12];

    float* out_h   = (float*)d_out;                                  // [4096,1024]
    float* out_pot = (float*)d_out + (size_t)B_DIM * OUT_DIM;        // [4096,2048]

    dim3 blk(256);
    dim3 g1(2 * OUT_DIM / BN, B_DIM / BM);   // 16 x 32
    dim3 g2(16, B_DIM / BM);                 // 8 z-blocks + 8 r-blocks, x 32
    dim3 g3(OUT_DIM / BN, B_DIM / BM);       // 8 x 32

    k_gemm_in<<<g1, blk>>>(x, h_prev, W_in, b_in, pot_prev, tresh, decay, out_pot);
    k_gemm_zr<<<g2, blk>>>(h_prev, W_z, b_z, W_r, b_r);
    k_gemm_n <<<g3, blk>>>(h_prev, W_n, b_n, out_h);
}

// round 12
// speedup vs baseline: 3.0219x; 3.0219x over previous
#include <cuda_runtime.h>
#include <cstdint>
#include <math.h>

#define BM 128
#define BN 128
#define BK 16

#define B_DIM   4096
#define IN_DIM  1024
#define OUT_DIM 1024

// ---------------- scratch (allocation-free rule) ----------------
// NOTE: these symbols are ONLY referenced from device code. Passing them as
// kernel arguments from host code silently passes the host shadow object
// (ATS makes it dereferenceable -> silent garbage). That was the R8/R9 bug.
__device__ float g_act[(size_t)B_DIM * 2 * OUT_DIM];   // activated [4096, 2048]
__device__ float g_z  [(size_t)B_DIM * OUT_DIM];       // z         [4096, 1024]
__device__ float g_hr [(size_t)B_DIM * OUT_DIM];       // h_prev*r  [4096, 1024]
__device__ float g_Wtz[(size_t)OUT_DIM * 3 * OUT_DIM]; // W_z^T [1024, 3072]
__device__ float g_Wtr[(size_t)OUT_DIM * 3 * OUT_DIM];
__device__ float g_Wtn[(size_t)OUT_DIM * 3 * OUT_DIM];

// ======================= helpers =======================
__device__ __forceinline__ uint32_t smem_u32(const void* p) {
    uint32_t a;
    asm("{ .reg .u64 t; cvta.to.shared.u64 t, %1; cvt.u32.u64 %0, t; }"
        : "=r"(a) : "l"(p));
    return a;
}
__device__ __forceinline__ void cpa16(uint32_t dst, const float* src) {
    asm volatile("cp.async.cg.shared.global [%0], [%1], 16;"
                 :: "r"(dst), "l"(src));
}
__device__ __forceinline__ void mma_tf32(float (&d)[4], const uint32_t (&a)[4],
                                         const uint32_t (&b)[2]) {
    asm volatile(
        "mma.sync.aligned.m16n8k8.row.col.f32.tf32.tf32.f32 "
        "{%0,%1,%2,%3}, {%4,%5,%6,%7}, {%8,%9}, {%0,%1,%2,%3};"
        : "+f"(d[0]), "+f"(d[1]), "+f"(d[2]), "+f"(d[3])
        : "r"(a[0]), "r"(a[1]), "r"(a[2]), "r"(a[3]),
          "r"(b[0]), "r"(b[1]));
}
__device__ __forceinline__ float sigmoidf_(float x) {
    return 1.0f / (1.0f + expf(-x));
}

// smem geometry for the mma gate kernels
#define GBK   32
#define GPAD  36
#define GBUF  (128 * GPAD)                       // 4608 floats per buffer
static constexpr int GATE_SMEM = 4 * GBUF * 4;   // 73728 B

// ======================= gate GEMM (mma.sync tf32) =======================
// D[128,128] tile of A[4096,3072] * Wt[1024,3072]^T.
// A = rowwise concat [g_act (K 0..2047) | (h_prev or g_hr) (K 2048..)].
// All scratch symbols resolved IN DEVICE CODE via the GATE template param.
static constexpr int GNST = 3072 / GBK;          // 96 stages

template <int GATE>
__global__ void __launch_bounds__(256, 2)
k_gate(const float* __restrict__ h_prev, const float* __restrict__ bias,
       float* __restrict__ out_h_arg)
{
    extern __shared__ float dsm[];
    const uint32_t sb = smem_u32(dsm);

    // device-side symbol selection (the fix)
    const float* A1 = (GATE == 2) ? g_hr : h_prev;
    const float* Wt = (GATE == 0) ? g_Wtz : (GATE == 1) ? g_Wtr : g_Wtn;
    float* outp     = (GATE == 0) ? g_z   : (GATE == 1) ? g_hr  : out_h_arg;

    const int bid = blockIdx.x;
    const int m0 = (bid >> 3) * 128;
    const int n0 = (bid & 7) * 128;

    const int tid = threadIdx.x;
    const int lane = tid & 31;
    const int wid = tid >> 5;
    const int gid = lane >> 2;         // 0..7
    const int tig = lane & 3;          // 0..3
    const int wm = (wid >> 2) * 64;    // warp m offset (0,64)
    const int wn = (wid & 3) * 32;     // warp n offset (0,32,64,96)

    float acc[4][4][4];
#pragma unroll
    for (int i = 0; i < 4; i++)
#pragma unroll
        for (int j = 0; j < 4; j++)
#pragma unroll
            for (int c = 0; c < 4; c++) acc[i][j][c] = 0.0f;

    auto issue_stage = [&](int s) {
        const int buf = s & 1;
        const int kk  = s * GBK;
        const float* As; int lda; int kc;
        if (kk < 2048) { As = g_act; lda = 2048; kc = kk; }
        else           { As = A1;    lda = 1024; kc = kk - 2048; }
        const uint32_t abase = sb + (uint32_t)(buf * GBUF) * 4u;
        const uint32_t bbase = sb + (uint32_t)((2 + buf) * GBUF) * 4u;
#pragma unroll
        for (int l = 0; l < 4; l++) {
            int c = tid + l * 256;          // 0..1023
            int row = c >> 3, q = c & 7;    // 128 rows x 8 float4
            cpa16(abase + (uint32_t)(row * GPAD + q * 4) * 4u,
                  As + (size_t)(m0 + row) * lda + kc + q * 4);
        }
#pragma unroll
        for (int l = 0; l < 4; l++) {
            int c = tid + l * 256;
            int row = c >> 3, q = c & 7;
            cpa16(bbase + (uint32_t)(row * GPAD + q * 4) * 4u,
                  Wt + (size_t)(n0 + row) * 3072 + kk + q * 4);
        }
        asm volatile("cp.async.commit_group;");
    };

    issue_stage(0);
    for (int s = 0; s < GNST; s++) {
        if (s + 1 < GNST) {
            issue_stage(s + 1);
            asm volatile("cp.async.wait_group 1;");
        } else {
            asm volatile("cp.async.wait_group 0;");
        }
        __syncthreads();

        const int buf = s & 1;
        const float* Ab = dsm + buf * GBUF;
        const float* Bb = dsm + (2 + buf) * GBUF;

#pragma unroll
        for (int kq = 0; kq < 4; kq++) {
            const int k0 = kq * 8;
            uint32_t af[4][4];
#pragma unroll
            for (int mt = 0; mt < 4; mt++) {
                const int r = wm + mt * 16 + gid;
                af[mt][0] = __float_as_uint(Ab[r * GPAD + k0 + tig]);
                af[mt][1] = __float_as_uint(Ab[(r + 8) * GPAD + k0 + tig]);
                af[mt][2] = __float_as_uint(Ab[r * GPAD + k0 + tig + 4]);
                af[mt][3] = __float_as_uint(Ab[(r + 8) * GPAD + k0 + tig + 4]);
            }
            uint32_t bf[4][2];
#pragma unroll
            for (int nt = 0; nt < 4; nt++) {
                const int c = wn + nt * 8 + gid;
                bf[nt][0] = __float_as_uint(Bb[c * GPAD + k0 + tig]);
                bf[nt][1] = __float_as_uint(Bb[c * GPAD + k0 + tig + 4]);
            }
#pragma unroll
            for (int mt = 0; mt < 4; mt++)
#pragma unroll
                for (int nt = 0; nt < 4; nt++)
                    mma_tf32(acc[mt][nt], af[mt], bf[nt]);
        }
        __syncthreads();
    }

    // --- epilogue: fused activation, direct reg->global (float2 stores) ---
#pragma unroll
    for (int mt = 0; mt < 4; mt++) {
#pragma unroll
        for (int nt = 0; nt < 4; nt++) {
            const int n = n0 + wn + nt * 8 + tig * 2;
            const float b0 = bias[n], b1 = bias[n + 1];
#pragma unroll
            for (int half = 0; half < 2; half++) {
                const int m = m0 + wm + mt * 16 + gid + half * 8;
                const size_t idx = (size_t)m * OUT_DIM + n;
                float v0 = acc[mt][nt][half * 2 + 0] + b0;
                float v1 = acc[mt][nt][half * 2 + 1] + b1;
                float2 o;
                if (GATE == 0) {                 // z = sigmoid
                    o.x = sigmoidf_(v0);
                    o.y = sigmoidf_(v1);
                } else if (GATE == 1) {          // hr = h * sigmoid(r)
                    float2 h = *(const float2*)(h_prev + idx);
                    o.x = h.x * sigmoidf_(v0);
                    o.y = h.y * sigmoidf_(v1);
                } else {                         // h_next = (1-z)h + z tanh(v)
                    float2 h = *(const float2*)(h_prev + idx);
                    float2 zz = *(const float2*)(g_z + idx);
                    o.x = fmaf(zz.x, tanhf(v0) - h.x, h.x);
                    o.y = fmaf(zz.y, tanhf(v1) - h.y, h.y);
                }
                *(float2*)(outp + idx) = o;
            }
        }
    }
}

// ---------------- weight transpose [3072,1024] -> [1024,3072] ----------------
// destination selected in device code (was already correct)
__global__ void k_tr(const float* __restrict__ W, int which)
{
    float* Wt = (which == 0) ? g_Wtz : (which == 1) ? g_Wtr : g_Wtn;
    __shared__ float t[32][33];
    const int bx = blockIdx.x, by = blockIdx.y;
    const int x = threadIdx.x, y = threadIdx.y;
#pragma unroll
    for (int i = 0; i < 32; i += 8)
        t[y + i][x] = W[(size_t)(by * 32 + y + i) * 1024 + bx * 32 + x];
    __syncthreads();
#pragma unroll
    for (int i = 0; i < 32; i += 8)
        Wt[(size_t)(bx * 32 + y + i) * 3072 + by * 32 + x] = t[x][y + i];
}

// ======================= fp32 SGEMM for W_in (R2, known-passing) =======================
__device__ __forceinline__ void gemm_main(
    const float* __restrict__ A0, int lda0, int K0,
    const float* __restrict__ A1, int lda1,
    const float* __restrict__ Bp, int ldb,
    int m0, int n0, int Ktot,
    float (&acc)[8][8])
{
    __shared__ float As[BK][BM + 4];
    __shared__ float Bs[BK][BN];

    const int tid = threadIdx.x;
    const int tx = tid & 15;
    const int ty = tid >> 4;

#pragma unroll
    for (int i = 0; i < 8; i++)
#pragma unroll
        for (int j = 0; j < 8; j++) acc[i][j] = 0.0f;

    for (int k0 = 0; k0 < Ktot; k0 += BK) {
        const float* Asrc;
        int lda, kk;
        if (k0 < K0) { Asrc = A0; lda = lda0; kk = k0; }
        else         { Asrc = A1; lda = lda1; kk = k0 - K0; }

#pragma unroll
        for (int l = 0; l < 2; l++) {
            int v  = tid + l * 256;
            int m  = v >> 2;
            int kq = (v & 3) * 4;
            float4 a = *(const float4*)(Asrc + (size_t)(m0 + m) * lda + kk + kq);
            As[kq + 0][m] = a.x;
            As[kq + 1][m] = a.y;
            As[kq + 2][m] = a.z;
            As[kq + 3][m] = a.w;
        }
#pragma unroll
        for (int l = 0; l < 2; l++) {
            int v  = tid + l * 256;
            int kr = v >> 5;
            int nq = (v & 31) * 4;
            *(float4*)&Bs[kr][nq] =
                *(const float4*)(Bp + (size_t)(k0 + kr) * ldb + n0 + nq);
        }
        __syncthreads();

#pragma unroll
        for (int k = 0; k < BK; k++) {
            float4 a0 = *(const float4*)&As[k][ty * 4];
            float4 a1 = *(const float4*)&As[k][64 + ty * 4];
            float4 b0 = *(const float4*)&Bs[k][tx * 4];
            float4 b1 = *(const float4*)&Bs[k][64 + tx * 4];
            float ra[8] = {a0.x, a0.y, a0.z, a0.w, a1.x, a1.y, a1.z, a1.w};
            float rb[8] = {b0.x, b0.y, b0.z, b0.w, b1.x, b1.y, b1.z, b1.w};
#pragma unroll
            for (int i = 0; i < 8; i++)
#pragma unroll
                for (int j = 0; j < 8; j++)
                    acc[i][j] = fmaf(ra[i], rb[j], acc[i][j]);
        }
        __syncthreads();
    }
}

__global__ void __launch_bounds__(256, 2)
k_gemm_in(const float* __restrict__ x, const float* __restrict__ h_prev,
          const float* __restrict__ W_in, const float* __restrict__ b_in,
          const float* __restrict__ pot_prev,
          const float* __restrict__ tresh, const float* __restrict__ decay,
          float* __restrict__ out_pot)
{
    const int n0 = blockIdx.x * BN;
    const int m0 = blockIdx.y * BM;
    float acc[8][8];
    gemm_main(x, IN_DIM, IN_DIM, h_prev, OUT_DIM,
              W_in, 2 * OUT_DIM, m0, n0, IN_DIM + OUT_DIM, acc);

    const int tx = threadIdx.x & 15;
    const int ty = threadIdx.x >> 4;
    const int rows[2] = {ty * 4, 64 + ty * 4};
    const int cols[2] = {tx * 4, 64 + tx * 4};

#pragma unroll
    for (int ih = 0; ih < 2; ih++)
#pragma unroll
        for (int i = 0; i < 4; i++) {
            const int m = m0 + rows[ih] + i;
#pragma unroll
            for (int jh = 0; jh < 2; jh++)
#pragma unroll
                for (int j = 0; j < 4; j++) {
                    const int n = n0 + cols[jh] + j;
                    float c  = acc[ih * 4 + i][jh * 4 + j] + b_in[n];
                    float pt = pot_prev[(size_t)m * (2 * OUT_DIM) + n] + c;
                    bool  sp = pt > tresh[n];
                    g_act[(size_t)m * (2 * OUT_DIM) + n]   = sp ? pt : 0.0f;
                    out_pot[(size_t)m * (2 * OUT_DIM) + n] = sp ? 0.0f : pt * decay[n];
                }
        }
}

// ======================= launch =======================
extern "C" void kernel_launch(void* const* d_in, const int* in_sizes, int n_in,
                              void* d_out, int out_size)
{
    const float* x        = (const float*)d_in[0];
    const float* h_prev   = (const float*)d_in[1];
    const float* pot_prev = (const float*)d_in[2];
    const float* W_in     = (const float*)d_in[3];
    const float* b_in     = (const float*)d_in[4];
    const float* tresh    = (const float*)d_in[5];
    const float* decay    = (const float*)d_in[6];
    const float* W_z      = (const float*)d_in[7];
    const float* b_z      = (const float*)d_in[8];
    const float* W_r      = (const float*)d_in[9];
    const float* b_r      = (const float*)d_in[10];
    const float* W_n      = (const float*)d_in[11];
    const float* b_n      = (const float*)d_in[12];

    float* out_h   = (float*)d_out;                                  // [4096,1024]
    float* out_pot = (float*)d_out + (size_t)B_DIM * OUT_DIM;        // [4096,2048]

    cudaFuncSetAttribute(k_gate<0>, cudaFuncAttributeMaxDynamicSharedMemorySize,
                         GATE_SMEM);
    cudaFuncSetAttribute(k_gate<1>, cudaFuncAttributeMaxDynamicSharedMemorySize,
                         GATE_SMEM);
    cudaFuncSetAttribute(k_gate<2>, cudaFuncAttributeMaxDynamicSharedMemorySize,
                         GATE_SMEM);

    dim3 blk(256);
    dim3 g1(2 * OUT_DIM / BN, B_DIM / BM);   // 16 x 32
    dim3 trb(32, 8);

    k_tr<<<dim3(32, 96), trb>>>(W_z, 0);
    k_tr<<<dim3(32, 96), trb>>>(W_r, 1);
    k_tr<<<dim3(32, 96), trb>>>(W_n, 2);

    // fp32 GEMM1 (known-good): writes g_act + pot_next
    k_gemm_in<<<g1, blk>>>(x, h_prev, W_in, b_in, pot_prev, tresh, decay, out_pot);

    // mma.sync tf32 gates: z and r independent; n depends on z & hr.
    // Only runtime pointers are passed; scratch symbols resolved device-side.
    k_gate<0><<<256, blk, GATE_SMEM>>>(h_prev, b_z, nullptr);
    k_gate<1><<<256, blk, GATE_SMEM>>>(h_prev, b_r, nullptr);
    k_gate<2><<<256, blk, GATE_SMEM>>>(h_prev, b_n, out_h);
}